// round 4
// baseline (speedup 1.0000x reference)
#include <cuda_runtime.h>
#include <math.h>

// Problem dims
#define Bsz 512
#define Ssz 10
#define Tsz 10
#define Esz 512
#define Hsz 512          // HB = HD
#define Dsz 1024         // dec hidden = HB + HD
#define Psz 512          // predictor input
#define PDsz 4
#define NROWS (Ssz*Bsz)  // 5120 (all segments batched for decoder)
#define G3H (3*Hsz)      // 1536
#define G3D (3*Dsz)      // 3072

// ---------------- scratch (device globals: no allocation allowed) ----------------
__device__ float g_emb[2][NROWS*Esz];        // relu embeddings [enc][s*B+b][E]
__device__ float g_gi[2][NROWS*G3H];         // precomputed encoder input gates
__device__ float g_hbuf[2][2][Bsz*Hsz];      // encoder hidden double-buffer [enc][parity]
__device__ float g_H[2][NROWS*Dsz];          // decoder hidden double-buffer
__device__ float g_PI[NROWS*Psz];            // decoder pred-input

__device__ __forceinline__ float sigmf(float x) { return 1.0f / (1.0f + __expf(-x)); }

// ---------------- embeddings: relu(x @ W + b), K=4 ----------------
__global__ void embed_kernel(const float* __restrict__ box, const float* __restrict__ dm,
                             const float* __restrict__ Wb, const float* __restrict__ bb,
                             const float* __restrict__ Wd, const float* __restrict__ bd)
{
    int idx = blockIdx.x * blockDim.x + threadIdx.x;
    if (idx >= NROWS * Esz) return;
    int e = idx % Esz;
    int sb = idx / Esz;
    int b = sb % Bsz, s = sb / Bsz;
    const float* x; const float* W; const float* bi; float* out;
    if (blockIdx.y == 0) { x = box; W = Wb; bi = bb; out = g_emb[0]; }
    else                 { x = dm;  W = Wd; bi = bd; out = g_emb[1]; }
    const float* xp = x + ((size_t)b * Ssz + s) * 4;
    float acc = bi[e];
#pragma unroll
    for (int k = 0; k < 4; k++) acc = fmaf(xp[k], W[(size_t)k * Esz + e], acc);
    out[idx] = fmaxf(acc, 0.0f);
}

// ---------------- generic NT GEMM + bias: C[M,N] = A[M,K] @ W[N,K]^T + bias ----------------
// BM=BN=128, BK=16, 256 threads, 8x8 microtile. M%128==0, N%128==0, K%16==0.
__global__ __launch_bounds__(256) void gemm_nt_bias_kernel(
    const float* __restrict__ A, const float* __restrict__ W,
    const float* __restrict__ bias, float* __restrict__ C,
    int K, int N)
{
    __shared__ float As[16][132];
    __shared__ float Ws[16][132];
    int tid = threadIdx.x;
    int tx = tid & 15, ty = tid >> 4;
    int m0 = blockIdx.y * 128, n0 = blockIdx.x * 128;
    float acc[8][8] = {};
    for (int k0 = 0; k0 < K; k0 += 16) {
#pragma unroll
        for (int i = 0; i < 2; i++) {
            int f = tid + i * 256;
            int r = f >> 2, c4 = (f & 3) * 4;
            float4 v = *(const float4*)(A + (size_t)(m0 + r) * K + k0 + c4);
            As[c4 + 0][r] = v.x; As[c4 + 1][r] = v.y; As[c4 + 2][r] = v.z; As[c4 + 3][r] = v.w;
            float4 w = *(const float4*)(W + (size_t)(n0 + r) * K + k0 + c4);
            Ws[c4 + 0][r] = w.x; Ws[c4 + 1][r] = w.y; Ws[c4 + 2][r] = w.z; Ws[c4 + 3][r] = w.w;
        }
        __syncthreads();
#pragma unroll
        for (int kk = 0; kk < 16; kk++) {
            float a[8], w[8];
#pragma unroll
            for (int i = 0; i < 8; i++) a[i] = As[kk][ty * 8 + i];
#pragma unroll
            for (int j = 0; j < 8; j++) w[j] = Ws[kk][tx * 8 + j];
#pragma unroll
            for (int i = 0; i < 8; i++)
#pragma unroll
                for (int j = 0; j < 8; j++)
                    acc[i][j] = fmaf(a[i], w[j], acc[i][j]);
        }
        __syncthreads();
    }
#pragma unroll
    for (int i = 0; i < 8; i++) {
        int m = m0 + ty * 8 + i;
#pragma unroll
        for (int j = 0; j < 8; j += 4) {
            int n = n0 + tx * 8 + j;
            float4 o;
            o.x = acc[i][j + 0] + bias[n + 0];
            o.y = acc[i][j + 1] + bias[n + 1];
            o.z = acc[i][j + 2] + bias[n + 2];
            o.w = acc[i][j + 3] + bias[n + 3];
            *(float4*)(C + (size_t)m * N + n) = o;
        }
    }
}

// ---------------- encoder recurrent step (fused gh-GEMM + GRU pointwise) ----------------
// One launch handles both encoders via blockIdx.z. Rows=B(512), units=H(512), K=H(512).
__global__ __launch_bounds__(256) void enc_step_kernel(
    int s, int par,
    const float* __restrict__ Whh0, const float* __restrict__ bhh0,
    const float* __restrict__ Whh1, const float* __restrict__ bhh1,
    float* __restrict__ H0out)
{
    int z = blockIdx.z;
    const float* Whh = z ? Whh1 : Whh0;
    const float* bhh = z ? bhh1 : bhh0;
    const float* hin = g_hbuf[z][par];
    float* hout = g_hbuf[z][par ^ 1];
    const float* gi = g_gi[z] + (size_t)s * Bsz * G3H;

    __shared__ float As[16][68];
    __shared__ float Ws[3][16][68];
    int tid = threadIdx.x;
    int tx = tid & 15, ty = tid >> 4;
    int m0 = blockIdx.y * 64, n0 = blockIdx.x * 64;
    float accR[4][4] = {}, accZ[4][4] = {}, accN[4][4] = {};

    for (int k0 = 0; k0 < Hsz; k0 += 16) {
        {
            int r = tid >> 2, c4 = (tid & 3) * 4;
            float4 v = *(const float4*)(hin + (size_t)(m0 + r) * Hsz + k0 + c4);
            As[c4 + 0][r] = v.x; As[c4 + 1][r] = v.y; As[c4 + 2][r] = v.z; As[c4 + 3][r] = v.w;
#pragma unroll
            for (int g = 0; g < 3; g++) {
                float4 w = *(const float4*)(Whh + (size_t)(g * Hsz + n0 + r) * Hsz + k0 + c4);
                Ws[g][c4 + 0][r] = w.x; Ws[g][c4 + 1][r] = w.y;
                Ws[g][c4 + 2][r] = w.z; Ws[g][c4 + 3][r] = w.w;
            }
        }
        __syncthreads();
#pragma unroll
        for (int kk = 0; kk < 16; kk++) {
            float a[4], wr[4], wz[4], wn[4];
#pragma unroll
            for (int i = 0; i < 4; i++) a[i] = As[kk][ty * 4 + i];
#pragma unroll
            for (int j = 0; j < 4; j++) {
                wr[j] = Ws[0][kk][tx * 4 + j];
                wz[j] = Ws[1][kk][tx * 4 + j];
                wn[j] = Ws[2][kk][tx * 4 + j];
            }
#pragma unroll
            for (int i = 0; i < 4; i++)
#pragma unroll
                for (int j = 0; j < 4; j++) {
                    accR[i][j] = fmaf(a[i], wr[j], accR[i][j]);
                    accZ[i][j] = fmaf(a[i], wz[j], accZ[i][j]);
                    accN[i][j] = fmaf(a[i], wn[j], accN[i][j]);
                }
        }
        __syncthreads();
    }
#pragma unroll
    for (int i = 0; i < 4; i++) {
        int m = m0 + ty * 4 + i;
#pragma unroll
        for (int j = 0; j < 4; j++) {
            int u = n0 + tx * 4 + j;
            float giR = gi[(size_t)m * G3H + u];
            float giZ = gi[(size_t)m * G3H + Hsz + u];
            float giN = gi[(size_t)m * G3H + 2 * Hsz + u];
            float r  = sigmf(giR + accR[i][j] + bhh[u]);
            float zt = sigmf(giZ + accZ[i][j] + bhh[Hsz + u]);
            float n  = tanhf(giN + r * (accN[i][j] + bhh[2 * Hsz + u]));
            float hold = hin[(size_t)m * Hsz + u];
            float hn = n + zt * (hold - n);
            hout[(size_t)m * Hsz + u] = hn;
            H0out[((size_t)s * Bsz + m) * Dsz + (size_t)z * Hsz + u] = hn;  // concat into dec h0
        }
    }
}

// ---------------- decoder step: fused gi(pi@Wih^T) + gh(h@Whh^T) + GRU pointwise ----------------
// Rows = 5120, units = 1024, 3 gates. BM=128, BN=64, BK=16, 8x4 microtile.
__global__ __launch_bounds__(256) void dec_step_kernel(
    const float* __restrict__ Hin, float* __restrict__ Hout,
    const float* __restrict__ Wih, const float* __restrict__ Whh,
    const float* __restrict__ bih, const float* __restrict__ bhh,
    float* __restrict__ dech, int t, int skip_x)
{
    __shared__ float As[16][132];
    __shared__ float Ws[3][16][68];
    int tid = threadIdx.x;
    int tx = tid & 15, ty = tid >> 4;
    int m0 = blockIdx.y * 128, n0 = blockIdx.x * 64;
    float accR[8][4] = {}, accZ[8][4] = {}, accNx[8][4] = {}, accNh[8][4] = {};

    // Phase X: gi += PI @ Wih^T   (K = Psz)    [skipped at t=0: pi == 0]
    if (!skip_x) {
        for (int k0 = 0; k0 < Psz; k0 += 16) {
#pragma unroll
            for (int i = 0; i < 2; i++) {
                int f = tid + i * 256;
                int r = f >> 2, c4 = (f & 3) * 4;
                float4 v = *(const float4*)(g_PI + (size_t)(m0 + r) * Psz + k0 + c4);
                As[c4 + 0][r] = v.x; As[c4 + 1][r] = v.y; As[c4 + 2][r] = v.z; As[c4 + 3][r] = v.w;
            }
            {
                int r = tid >> 2, c4 = (tid & 3) * 4;
#pragma unroll
                for (int g = 0; g < 3; g++) {
                    float4 w = *(const float4*)(Wih + (size_t)(g * Dsz + n0 + r) * Psz + k0 + c4);
                    Ws[g][c4 + 0][r] = w.x; Ws[g][c4 + 1][r] = w.y;
                    Ws[g][c4 + 2][r] = w.z; Ws[g][c4 + 3][r] = w.w;
                }
            }
            __syncthreads();
#pragma unroll
            for (int kk = 0; kk < 16; kk++) {
                float a[8], wr[4], wz[4], wn[4];
#pragma unroll
                for (int i = 0; i < 8; i++) a[i] = As[kk][ty * 8 + i];
#pragma unroll
                for (int j = 0; j < 4; j++) {
                    wr[j] = Ws[0][kk][tx * 4 + j];
                    wz[j] = Ws[1][kk][tx * 4 + j];
                    wn[j] = Ws[2][kk][tx * 4 + j];
                }
#pragma unroll
                for (int i = 0; i < 8; i++)
#pragma unroll
                    for (int j = 0; j < 4; j++) {
                        accR[i][j]  = fmaf(a[i], wr[j], accR[i][j]);
                        accZ[i][j]  = fmaf(a[i], wz[j], accZ[i][j]);
                        accNx[i][j] = fmaf(a[i], wn[j], accNx[i][j]);
                    }
            }
            __syncthreads();
        }
    }

    // Phase H: gh += H @ Whh^T   (K = Dsz)
    for (int k0 = 0; k0 < Dsz; k0 += 16) {
#pragma unroll
        for (int i = 0; i < 2; i++) {
            int f = tid + i * 256;
            int r = f >> 2, c4 = (f & 3) * 4;
            float4 v = *(const float4*)(Hin + (size_t)(m0 + r) * Dsz + k0 + c4);
            As[c4 + 0][r] = v.x; As[c4 + 1][r] = v.y; As[c4 + 2][r] = v.z; As[c4 + 3][r] = v.w;
        }
        {
            int r = tid >> 2, c4 = (tid & 3) * 4;
#pragma unroll
            for (int g = 0; g < 3; g++) {
                float4 w = *(const float4*)(Whh + (size_t)(g * Dsz + n0 + r) * Dsz + k0 + c4);
                Ws[g][c4 + 0][r] = w.x; Ws[g][c4 + 1][r] = w.y;
                Ws[g][c4 + 2][r] = w.z; Ws[g][c4 + 3][r] = w.w;
            }
        }
        __syncthreads();
#pragma unroll
        for (int kk = 0; kk < 16; kk++) {
            float a[8], wr[4], wz[4], wn[4];
#pragma unroll
            for (int i = 0; i < 8; i++) a[i] = As[kk][ty * 8 + i];
#pragma unroll
            for (int j = 0; j < 4; j++) {
                wr[j] = Ws[0][kk][tx * 4 + j];
                wz[j] = Ws[1][kk][tx * 4 + j];
                wn[j] = Ws[2][kk][tx * 4 + j];
            }
#pragma unroll
            for (int i = 0; i < 8; i++)
#pragma unroll
                for (int j = 0; j < 4; j++) {
                    accR[i][j]  = fmaf(a[i], wr[j], accR[i][j]);
                    accZ[i][j]  = fmaf(a[i], wz[j], accZ[i][j]);
                    accNh[i][j] = fmaf(a[i], wn[j], accNh[i][j]);
                }
        }
        __syncthreads();
    }

    // GRU pointwise + output write
#pragma unroll
    for (int i = 0; i < 8; i++) {
        int m = m0 + ty * 8 + i;
        int b = m & (Bsz - 1);
        int s = m >> 9;
#pragma unroll
        for (int j = 0; j < 4; j++) {
            int u = n0 + tx * 4 + j;
            float r  = sigmf(accR[i][j] + bih[u] + bhh[u]);
            float zt = sigmf(accZ[i][j] + bih[Dsz + u] + bhh[Dsz + u]);
            float n  = tanhf(accNx[i][j] + bih[2 * Dsz + u] + r * (accNh[i][j] + bhh[2 * Dsz + u]));
            float hold = Hin[(size_t)m * Dsz + u];
            float hn = n + zt * (hold - n);
            Hout[(size_t)m * Dsz + u] = hn;
            dech[(((size_t)b * Ssz + s) * Tsz + t) * Dsz + u] = hn;
        }
    }
}

// ---------------- pi = relu(h @ W_h2pi + b)  (NN GEMM: W is [D, P], N-contiguous) ----------------
// BM=BN=128, BK=16, 8x8 microtile.
__global__ __launch_bounds__(256) void pi_kernel(
    const float* __restrict__ Hcur, const float* __restrict__ W,
    const float* __restrict__ bias)
{
    __shared__ float As[16][132];
    __shared__ float Ws[16][132];
    int tid = threadIdx.x;
    int tx = tid & 15, ty = tid >> 4;
    int m0 = blockIdx.y * 128, n0 = blockIdx.x * 128;
    float acc[8][8] = {};
    for (int k0 = 0; k0 < Dsz; k0 += 16) {
#pragma unroll
        for (int i = 0; i < 2; i++) {
            int f = tid + i * 256;
            {   // A (transpose-store)
                int r = f >> 2, c4 = (f & 3) * 4;
                float4 v = *(const float4*)(Hcur + (size_t)(m0 + r) * Dsz + k0 + c4);
                As[c4 + 0][r] = v.x; As[c4 + 1][r] = v.y; As[c4 + 2][r] = v.z; As[c4 + 3][r] = v.w;
            }
            {   // W (direct store, already k-major rows)
                int kk = f >> 5, nq = (f & 31) * 4;
                float4 w = *(const float4*)(W + (size_t)(k0 + kk) * Psz + n0 + nq);
                *(float4*)&Ws[kk][nq] = w;
            }
        }
        __syncthreads();
#pragma unroll
        for (int kk = 0; kk < 16; kk++) {
            float a[8], w[8];
#pragma unroll
            for (int i = 0; i < 8; i++) a[i] = As[kk][ty * 8 + i];
#pragma unroll
            for (int j = 0; j < 8; j++) w[j] = Ws[kk][tx * 8 + j];
#pragma unroll
            for (int i = 0; i < 8; i++)
#pragma unroll
                for (int j = 0; j < 8; j++)
                    acc[i][j] = fmaf(a[i], w[j], acc[i][j]);
        }
        __syncthreads();
    }
#pragma unroll
    for (int i = 0; i < 8; i++) {
        int m = m0 + ty * 8 + i;
#pragma unroll
        for (int j = 0; j < 8; j += 4) {
            int n = n0 + tx * 8 + j;
            float4 o;
            o.x = fmaxf(acc[i][j + 0] + bias[n + 0], 0.0f);
            o.y = fmaxf(acc[i][j + 1] + bias[n + 1], 0.0f);
            o.z = fmaxf(acc[i][j + 2] + bias[n + 2], 0.0f);
            o.w = fmaxf(acc[i][j + 3] + bias[n + 3], 0.0f);
            *(float4*)(g_PI + (size_t)m * Psz + n) = o;
        }
    }
}

// ---------------- out = tanh(h @ W_h2p + b), N = 4 (warp-per-row reduction) ----------------
__global__ void out_kernel(const float* __restrict__ Hcur,
                           const float* __restrict__ W, const float* __restrict__ bias,
                           float* __restrict__ preds, int t)
{
    int gtid = blockIdx.x * blockDim.x + threadIdx.x;
    int warp = gtid >> 5;
    int lane = threadIdx.x & 31;
    if (warp >= NROWS) return;
    const float* h = Hcur + (size_t)warp * Dsz;
    float ax = 0.f, ay = 0.f, az = 0.f, aw = 0.f;
    for (int d = lane; d < Dsz; d += 32) {
        float hv = h[d];
        float4 w = *(const float4*)(W + (size_t)d * 4);
        ax = fmaf(hv, w.x, ax); ay = fmaf(hv, w.y, ay);
        az = fmaf(hv, w.z, az); aw = fmaf(hv, w.w, aw);
    }
#pragma unroll
    for (int o = 16; o > 0; o >>= 1) {
        ax += __shfl_xor_sync(0xFFFFFFFFu, ax, o);
        ay += __shfl_xor_sync(0xFFFFFFFFu, ay, o);
        az += __shfl_xor_sync(0xFFFFFFFFu, az, o);
        aw += __shfl_xor_sync(0xFFFFFFFFu, aw, o);
    }
    if (lane == 0) {
        int b = warp & (Bsz - 1);
        int s = warp >> 9;
        float4 o;
        o.x = tanhf(ax + bias[0]);
        o.y = tanhf(ay + bias[1]);
        o.z = tanhf(az + bias[2]);
        o.w = tanhf(aw + bias[3]);
        *(float4*)(preds + (((size_t)b * Ssz + s) * Tsz + t) * 4) = o;
    }
}

// ---------------- host ----------------
extern "C" void kernel_launch(void* const* d_in, const int* in_sizes, int n_in,
                              void* d_out, int out_size)
{
    const float* box      = (const float*)d_in[0];
    const float* dm       = (const float*)d_in[1];
    const float* Wbe      = (const float*)d_in[2];
    const float* bbe      = (const float*)d_in[3];
    const float* Wde      = (const float*)d_in[4];
    const float* bde      = (const float*)d_in[5];
    const float* Wih_box  = (const float*)d_in[6];
    const float* Whh_box  = (const float*)d_in[7];
    const float* bih_box  = (const float*)d_in[8];
    const float* bhh_box  = (const float*)d_in[9];
    const float* Wih_dm   = (const float*)d_in[10];
    const float* Whh_dm   = (const float*)d_in[11];
    const float* bih_dm   = (const float*)d_in[12];
    const float* bhh_dm   = (const float*)d_in[13];
    const float* Wih_dec  = (const float*)d_in[14];
    const float* Whh_dec  = (const float*)d_in[15];
    const float* bih_dec  = (const float*)d_in[16];
    const float* bhh_dec  = (const float*)d_in[17];
    const float* W_h2pi   = (const float*)d_in[18];
    const float* b_h2pi   = (const float*)d_in[19];
    const float* W_h2p    = (const float*)d_in[20];
    const float* b_h2p    = (const float*)d_in[21];

    float* preds = (float*)d_out;                                      // [B,S,T,4]
    float* dech  = (float*)d_out + (size_t)Bsz * Ssz * Tsz * PDsz;     // [B,S,T,D]

    void *p_emb, *p_gi, *p_hbuf, *p_H, *p_PI;
    cudaGetSymbolAddress(&p_emb, g_emb);
    cudaGetSymbolAddress(&p_gi, g_gi);
    cudaGetSymbolAddress(&p_hbuf, g_hbuf);
    cudaGetSymbolAddress(&p_H, g_H);
    cudaGetSymbolAddress(&p_PI, g_PI);
    float* emb0 = (float*)p_emb;
    float* emb1 = emb0 + (size_t)NROWS * Esz;
    float* gi0  = (float*)p_gi;
    float* gi1  = gi0 + (size_t)NROWS * G3H;
    float* H0   = (float*)p_H;
    float* H1   = H0 + (size_t)NROWS * Dsz;

    // zero initial encoder hiddens + initial pred-input
    cudaMemsetAsync(p_hbuf, 0, sizeof(float) * 2 * 2 * Bsz * Hsz);
    cudaMemsetAsync(p_PI, 0, sizeof(float) * (size_t)NROWS * Psz);

    // embeddings (both encoders)
    {
        dim3 grid((NROWS * Esz + 255) / 256, 2);
        embed_kernel<<<grid, 256>>>(box, dm, Wbe, bbe, Wde, bde);
    }
    // encoder input gates precompute: gi = emb @ Wih^T + bih, for all segments at once
    {
        dim3 grid(G3H / 128, NROWS / 128);
        gemm_nt_bias_kernel<<<grid, 256>>>(emb0, Wih_box, bih_box, gi0, Esz, G3H);
        gemm_nt_bias_kernel<<<grid, 256>>>(emb1, Wih_dm,  bih_dm,  gi1, Esz, G3H);
    }
    // encoder recurrence (sequential over segments; both GRUs per launch)
    for (int s = 0; s < Ssz; s++) {
        dim3 grid(Hsz / 64, Bsz / 64, 2);
        enc_step_kernel<<<grid, 256>>>(s, s & 1, Whh_box, bhh_box, Whh_dm, bhh_dm, H0);
    }
    // decoder: 10 sequential steps at batch 5120 (all segments in parallel)
    for (int t = 0; t < Tsz; t++) {
        float* hin  = (t & 1) ? H1 : H0;
        float* hout = (t & 1) ? H0 : H1;
        {
            dim3 grid(Dsz / 64, NROWS / 128);
            dec_step_kernel<<<grid, 256>>>(hin, hout, Wih_dec, Whh_dec,
                                           bih_dec, bhh_dec, dech, t, t == 0 ? 1 : 0);
        }
        if (t < Tsz - 1) {
            dim3 grid(Psz / 128, NROWS / 128);
            pi_kernel<<<grid, 256>>>(hout, W_h2pi, b_h2pi);
        }
        out_kernel<<<(NROWS * 32 + 255) / 256, 256>>>(hout, W_h2p, b_h2p, preds, t);
    }
}

// round 5
// speedup vs baseline: 1.2027x; 1.2027x over previous
#include <cuda_runtime.h>
#include <math.h>
#include <stdint.h>

// Problem dims
#define Bsz 512
#define Ssz 10
#define Tsz 10
#define Esz 512
#define Hsz 512          // HB = HD
#define Dsz 1024         // dec hidden = HB + HD
#define Psz 512          // predictor input
#define PDsz 4
#define NROWS (Ssz*Bsz)  // 5120
#define G3H (3*Hsz)      // 1536

// ---------------- scratch ----------------
__device__ float g_emb[2][NROWS*Esz];
__device__ float g_gi[2][NROWS*G3H];
__device__ float g_hbuf[2][2][Bsz*Hsz];
__device__ float g_H[2][NROWS*Dsz];
__device__ float g_PI[NROWS*Psz];

__device__ __forceinline__ float sigmf(float x) { return 1.0f / (1.0f + __expf(-x)); }

// tf32 split: v = hi + lo, hi = round_to_tf32(v)
__device__ __forceinline__ void split2(float v, float& hi, float& lo) {
    uint32_t h;
    asm("cvt.rna.tf32.f32 %0, %1;" : "=r"(h) : "f"(v));
    float hf = __uint_as_float(h);
    hi = hf; lo = v - hf;
}

// m16n8k8 tf32 mma: c += a(16x8 row) * b(8x8 col)
__device__ __forceinline__ void mma8(float* c, const uint32_t* a, const uint32_t* b) {
    asm("mma.sync.aligned.m16n8k8.row.col.f32.tf32.tf32.f32 "
        "{%0,%1,%2,%3}, {%4,%5,%6,%7}, {%8,%9}, {%0,%1,%2,%3};"
        : "+f"(c[0]), "+f"(c[1]), "+f"(c[2]), "+f"(c[3])
        : "r"(a[0]), "r"(a[1]), "r"(a[2]), "r"(a[3]), "r"(b[0]), "r"(b[1]));
}

// ---------------- embeddings: relu(x @ W + b), K=4 ----------------
__global__ void embed_kernel(const float* __restrict__ box, const float* __restrict__ dm,
                             const float* __restrict__ Wb, const float* __restrict__ bb,
                             const float* __restrict__ Wd, const float* __restrict__ bd)
{
    int idx = blockIdx.x * blockDim.x + threadIdx.x;
    if (idx >= NROWS * Esz) return;
    int e = idx % Esz;
    int sb = idx / Esz;
    int b = sb % Bsz, s = sb / Bsz;
    const float* x; const float* W; const float* bi; float* out;
    if (blockIdx.y == 0) { x = box; W = Wb; bi = bb; out = g_emb[0]; }
    else                 { x = dm;  W = Wd; bi = bd; out = g_emb[1]; }
    const float* xp = x + ((size_t)b * Ssz + s) * 4;
    float acc = bi[e];
#pragma unroll
    for (int k = 0; k < 4; k++) acc = fmaf(xp[k], W[(size_t)k * Esz + e], acc);
    out[idx] = fmaxf(acc, 0.0f);
}

// ---------------- generic tf32 GEMM: C[M,Nn] = A[M,K] @ B + bias (opt relu) ----------------
// BT=true: B is [Nn,K] row-major (NT).  BT=false: B is [K,Nn] row-major (NN).
// Block 128Mx64N, 8 warps (4Mx2N), warp 32x32, 3xTF32.
template <int ACT, bool BT>
__global__ __launch_bounds__(256) void gemm_tf32(
    const float* __restrict__ A, int K,
    const float* __restrict__ B, const float* __restrict__ bias,
    float* __restrict__ C, int Nn)
{
    __shared__ float Ah[16][132], Al[16][132];
    __shared__ float Wh[16][72], Wl[16][72];
    int tid = threadIdx.x, lane = tid & 31, wid = tid >> 5;
    int wm = wid & 3, wn = wid >> 2;
    int m0 = blockIdx.y * 128, n0 = blockIdx.x * 64;
    int r = lane >> 2, cq = lane & 3;
    float acc[2][4][4] = {};

    for (int k0 = 0; k0 < K; k0 += 16) {
#pragma unroll
        for (int i = 0; i < 2; i++) {
            int f = tid + i * 256;
            int rr = f >> 2, c4 = (f & 3) * 4;
            float4 v = *(const float4*)(A + (size_t)(m0 + rr) * K + k0 + c4);
            split2(v.x, Ah[c4 + 0][rr], Al[c4 + 0][rr]);
            split2(v.y, Ah[c4 + 1][rr], Al[c4 + 1][rr]);
            split2(v.z, Ah[c4 + 2][rr], Al[c4 + 2][rr]);
            split2(v.w, Ah[c4 + 3][rr], Al[c4 + 3][rr]);
        }
        if (BT) {
            int rr = tid >> 2, c4 = (tid & 3) * 4;   // rr = n 0..63
            float4 v = *(const float4*)(B + (size_t)(n0 + rr) * K + k0 + c4);
            split2(v.x, Wh[c4 + 0][rr], Wl[c4 + 0][rr]);
            split2(v.y, Wh[c4 + 1][rr], Wl[c4 + 1][rr]);
            split2(v.z, Wh[c4 + 2][rr], Wl[c4 + 2][rr]);
            split2(v.w, Wh[c4 + 3][rr], Wl[c4 + 3][rr]);
        } else {
            int kk_ = tid >> 4, n4 = (tid & 15) * 4;
            float4 v = *(const float4*)(B + (size_t)(k0 + kk_) * Nn + n0 + n4);
            split2(v.x, Wh[kk_][n4 + 0], Wl[kk_][n4 + 0]);
            split2(v.y, Wh[kk_][n4 + 1], Wl[kk_][n4 + 1]);
            split2(v.z, Wh[kk_][n4 + 2], Wl[kk_][n4 + 2]);
            split2(v.w, Wh[kk_][n4 + 3], Wl[kk_][n4 + 3]);
        }
        __syncthreads();
#pragma unroll
        for (int kk = 0; kk < 16; kk += 8) {
            uint32_t ah[2][4], al[2][4];
#pragma unroll
            for (int mf = 0; mf < 2; mf++) {
                int mb = wm * 32 + mf * 16 + r;
                ah[mf][0] = __float_as_uint(Ah[kk + cq][mb]);
                ah[mf][1] = __float_as_uint(Ah[kk + cq][mb + 8]);
                ah[mf][2] = __float_as_uint(Ah[kk + cq + 4][mb]);
                ah[mf][3] = __float_as_uint(Ah[kk + cq + 4][mb + 8]);
                al[mf][0] = __float_as_uint(Al[kk + cq][mb]);
                al[mf][1] = __float_as_uint(Al[kk + cq][mb + 8]);
                al[mf][2] = __float_as_uint(Al[kk + cq + 4][mb]);
                al[mf][3] = __float_as_uint(Al[kk + cq + 4][mb + 8]);
            }
#pragma unroll
            for (int nf = 0; nf < 4; nf++) {
                int nb = wn * 32 + nf * 8 + r;
                uint32_t bh[2], bl[2];
                bh[0] = __float_as_uint(Wh[kk + cq][nb]);
                bh[1] = __float_as_uint(Wh[kk + cq + 4][nb]);
                bl[0] = __float_as_uint(Wl[kk + cq][nb]);
                bl[1] = __float_as_uint(Wl[kk + cq + 4][nb]);
#pragma unroll
                for (int mf = 0; mf < 2; mf++) {
                    mma8(acc[mf][nf], ah[mf], bh);
                    mma8(acc[mf][nf], ah[mf], bl);
                    mma8(acc[mf][nf], al[mf], bh);
                }
            }
        }
        __syncthreads();
    }
#pragma unroll
    for (int nf = 0; nf < 4; nf++) {
        int u = n0 + wn * 32 + nf * 8 + 2 * cq;
        float2 bi2 = *(const float2*)(bias + u);
#pragma unroll
        for (int mf = 0; mf < 2; mf++) {
#pragma unroll
            for (int half = 0; half < 2; half++) {
                int m = m0 + wm * 32 + mf * 16 + r + half * 8;
                float vx = acc[mf][nf][half * 2 + 0] + bi2.x;
                float vy = acc[mf][nf][half * 2 + 1] + bi2.y;
                if (ACT == 1) { vx = fmaxf(vx, 0.0f); vy = fmaxf(vy, 0.0f); }
                float2 o = {vx, vy};
                *(float2*)(C + (size_t)m * Nn + u) = o;
            }
        }
    }
}

// ---------------- encoder recurrent step (tf32 mma, fused GRU pointwise) ----------------
// Block 64Mx32N units, 8 warps (2Mx4N), warp 32Mx8N, 3 gates.
__global__ __launch_bounds__(256) void enc_step_mma(
    int s, int par,
    const float* __restrict__ Whh0, const float* __restrict__ bhh0,
    const float* __restrict__ Whh1, const float* __restrict__ bhh1,
    float* __restrict__ H0out)
{
    int z = blockIdx.z;
    const float* Whh = z ? Whh1 : Whh0;
    const float* bhh = z ? bhh1 : bhh0;
    const float* hin = g_hbuf[z][par];
    float* hout = g_hbuf[z][par ^ 1];
    const float* gi = g_gi[z] + (size_t)s * Bsz * G3H;

    __shared__ float Ah[16][68], Al[16][68];
    __shared__ float Wh[3][16][36], Wl[3][16][36];
    int tid = threadIdx.x, lane = tid & 31, wid = tid >> 5;
    int wm = wid & 1, wn = wid >> 1;
    int m0 = blockIdx.y * 64, n0 = blockIdx.x * 32;
    int r = lane >> 2, cq = lane & 3;
    float accR[2][4] = {}, accZ[2][4] = {}, accN[2][4] = {};

    for (int k0 = 0; k0 < Hsz; k0 += 16) {
        {
            int rr = tid >> 2, c4 = (tid & 3) * 4;   // 64 rows
            float4 v = *(const float4*)(hin + (size_t)(m0 + rr) * Hsz + k0 + c4);
            split2(v.x, Ah[c4 + 0][rr], Al[c4 + 0][rr]);
            split2(v.y, Ah[c4 + 1][rr], Al[c4 + 1][rr]);
            split2(v.z, Ah[c4 + 2][rr], Al[c4 + 2][rr]);
            split2(v.w, Ah[c4 + 3][rr], Al[c4 + 3][rr]);
        }
#pragma unroll
        for (int i = 0; i < 2; i++) {
            int f = tid + i * 256;
            if (f < 384) {
                int gr = f >> 2, c4 = (f & 3) * 4;
                int g = gr >> 5, nn = gr & 31;
                float4 v = *(const float4*)(Whh + (size_t)(g * Hsz + n0 + nn) * Hsz + k0 + c4);
                split2(v.x, Wh[g][c4 + 0][nn], Wl[g][c4 + 0][nn]);
                split2(v.y, Wh[g][c4 + 1][nn], Wl[g][c4 + 1][nn]);
                split2(v.z, Wh[g][c4 + 2][nn], Wl[g][c4 + 2][nn]);
                split2(v.w, Wh[g][c4 + 3][nn], Wl[g][c4 + 3][nn]);
            }
        }
        __syncthreads();
#pragma unroll
        for (int kk = 0; kk < 16; kk += 8) {
            uint32_t ah[2][4], al[2][4];
#pragma unroll
            for (int mf = 0; mf < 2; mf++) {
                int mb = wm * 32 + mf * 16 + r;
                ah[mf][0] = __float_as_uint(Ah[kk + cq][mb]);
                ah[mf][1] = __float_as_uint(Ah[kk + cq][mb + 8]);
                ah[mf][2] = __float_as_uint(Ah[kk + cq + 4][mb]);
                ah[mf][3] = __float_as_uint(Ah[kk + cq + 4][mb + 8]);
                al[mf][0] = __float_as_uint(Al[kk + cq][mb]);
                al[mf][1] = __float_as_uint(Al[kk + cq][mb + 8]);
                al[mf][2] = __float_as_uint(Al[kk + cq + 4][mb]);
                al[mf][3] = __float_as_uint(Al[kk + cq + 4][mb + 8]);
            }
#pragma unroll
            for (int g = 0; g < 3; g++) {
                int nb = wn * 8 + r;
                uint32_t bh[2], bl[2];
                bh[0] = __float_as_uint(Wh[g][kk + cq][nb]);
                bh[1] = __float_as_uint(Wh[g][kk + cq + 4][nb]);
                bl[0] = __float_as_uint(Wl[g][kk + cq][nb]);
                bl[1] = __float_as_uint(Wl[g][kk + cq + 4][nb]);
#pragma unroll
                for (int mf = 0; mf < 2; mf++) {
                    float* cc = (g == 0) ? accR[mf] : (g == 1) ? accZ[mf] : accN[mf];
                    mma8(cc, ah[mf], bh);
                    mma8(cc, ah[mf], bl);
                    mma8(cc, al[mf], bh);
                }
            }
        }
        __syncthreads();
    }
    // epilogue
    int u = n0 + wn * 8 + 2 * cq;
    float2 bR = *(const float2*)(bhh + u);
    float2 bZ = *(const float2*)(bhh + Hsz + u);
    float2 bN = *(const float2*)(bhh + 2 * Hsz + u);
#pragma unroll
    for (int mf = 0; mf < 2; mf++) {
#pragma unroll
        for (int half = 0; half < 2; half++) {
            int m = m0 + wm * 32 + mf * 16 + r + half * 8;
            float2 giR = *(const float2*)(gi + (size_t)m * G3H + u);
            float2 giZ = *(const float2*)(gi + (size_t)m * G3H + Hsz + u);
            float2 giN = *(const float2*)(gi + (size_t)m * G3H + 2 * Hsz + u);
            float2 hold = *(const float2*)(hin + (size_t)m * Hsz + u);
            int c0 = half * 2;
            float rx = sigmf(giR.x + accR[mf][c0 + 0] + bR.x);
            float ry = sigmf(giR.y + accR[mf][c0 + 1] + bR.y);
            float zx = sigmf(giZ.x + accZ[mf][c0 + 0] + bZ.x);
            float zy = sigmf(giZ.y + accZ[mf][c0 + 1] + bZ.y);
            float nx = tanhf(giN.x + rx * (accN[mf][c0 + 0] + bN.x));
            float ny = tanhf(giN.y + ry * (accN[mf][c0 + 1] + bN.y));
            float2 o;
            o.x = nx + zx * (hold.x - nx);
            o.y = ny + zy * (hold.y - ny);
            *(float2*)(hout + (size_t)m * Hsz + u) = o;
            *(float2*)(H0out + ((size_t)s * Bsz + m) * Dsz + (size_t)z * Hsz + u) = o;
        }
    }
}

// ---------------- decoder step (tf32 mma, fused two-phase GRU) ----------------
// Block 128Mx32N units, 8 warps (4Mx2N), warp 32Mx16N, 3 gates x 2 phases.
#define DEC_PHASE(APTR, KDIM, WPTR, ACCN)                                              \
    for (int k0 = 0; k0 < (KDIM); k0 += 16) {                                          \
        _Pragma("unroll")                                                              \
        for (int i = 0; i < 2; i++) {                                                  \
            int f = tid + i * 256;                                                     \
            int rr = f >> 2, c4 = (f & 3) * 4;                                         \
            float4 v = *(const float4*)((APTR) + (size_t)(m0 + rr) * (KDIM) + k0 + c4);\
            split2(v.x, Ah[c4 + 0][rr], Al[c4 + 0][rr]);                               \
            split2(v.y, Ah[c4 + 1][rr], Al[c4 + 1][rr]);                               \
            split2(v.z, Ah[c4 + 2][rr], Al[c4 + 2][rr]);                               \
            split2(v.w, Ah[c4 + 3][rr], Al[c4 + 3][rr]);                               \
        }                                                                              \
        _Pragma("unroll")                                                              \
        for (int i = 0; i < 2; i++) {                                                  \
            int f = tid + i * 256;                                                     \
            if (f < 384) {                                                             \
                int gr = f >> 2, c4 = (f & 3) * 4;                                     \
                int g = gr >> 5, nn = gr & 31;                                         \
                float4 v = *(const float4*)((WPTR) +                                   \
                    (size_t)(g * Dsz + n0 + nn) * (KDIM) + k0 + c4);                   \
                split2(v.x, Wh[g][c4 + 0][nn], Wl[g][c4 + 0][nn]);                     \
                split2(v.y, Wh[g][c4 + 1][nn], Wl[g][c4 + 1][nn]);                     \
                split2(v.z, Wh[g][c4 + 2][nn], Wl[g][c4 + 2][nn]);                     \
                split2(v.w, Wh[g][c4 + 3][nn], Wl[g][c4 + 3][nn]);                     \
            }                                                                          \
        }                                                                              \
        __syncthreads();                                                               \
        _Pragma("unroll")                                                              \
        for (int kk = 0; kk < 16; kk += 8) {                                           \
            uint32_t ah[2][4], al[2][4];                                               \
            _Pragma("unroll")                                                          \
            for (int mf = 0; mf < 2; mf++) {                                           \
                int mb = wm * 32 + mf * 16 + r;                                        \
                ah[mf][0] = __float_as_uint(Ah[kk + cq][mb]);                          \
                ah[mf][1] = __float_as_uint(Ah[kk + cq][mb + 8]);                      \
                ah[mf][2] = __float_as_uint(Ah[kk + cq + 4][mb]);                      \
                ah[mf][3] = __float_as_uint(Ah[kk + cq + 4][mb + 8]);                  \
                al[mf][0] = __float_as_uint(Al[kk + cq][mb]);                          \
                al[mf][1] = __float_as_uint(Al[kk + cq][mb + 8]);                      \
                al[mf][2] = __float_as_uint(Al[kk + cq + 4][mb]);                      \
                al[mf][3] = __float_as_uint(Al[kk + cq + 4][mb + 8]);                  \
            }                                                                          \
            _Pragma("unroll")                                                          \
            for (int g = 0; g < 3; g++) {                                              \
                _Pragma("unroll")                                                      \
                for (int nf = 0; nf < 2; nf++) {                                       \
                    int nb = wn * 16 + nf * 8 + r;                                     \
                    uint32_t bh[2], bl[2];                                             \
                    bh[0] = __float_as_uint(Wh[g][kk + cq][nb]);                       \
                    bh[1] = __float_as_uint(Wh[g][kk + cq + 4][nb]);                   \
                    bl[0] = __float_as_uint(Wl[g][kk + cq][nb]);                       \
                    bl[1] = __float_as_uint(Wl[g][kk + cq + 4][nb]);                   \
                    _Pragma("unroll")                                                  \
                    for (int mf = 0; mf < 2; mf++) {                                   \
                        float* cc = (g == 0) ? accR[mf][nf]                            \
                                  : (g == 1) ? accZ[mf][nf] : (ACCN)[mf][nf];          \
                        mma8(cc, ah[mf], bh);                                          \
                        mma8(cc, ah[mf], bl);                                          \
                        mma8(cc, al[mf], bh);                                          \
                    }                                                                  \
                }                                                                      \
            }                                                                          \
        }                                                                              \
        __syncthreads();                                                               \
    }

__global__ __launch_bounds__(256) void dec_step_mma(
    const float* __restrict__ Hin, float* __restrict__ Hout,
    const float* __restrict__ Wih, const float* __restrict__ Whh,
    const float* __restrict__ bih, const float* __restrict__ bhh,
    float* __restrict__ dech, int t)
{
    __shared__ float Ah[16][132], Al[16][132];
    __shared__ float Wh[3][16][36], Wl[3][16][36];
    int tid = threadIdx.x, lane = tid & 31, wid = tid >> 5;
    int wm = wid & 3, wn = wid >> 2;
    int m0 = blockIdx.y * 128, n0 = blockIdx.x * 32;
    int r = lane >> 2, cq = lane & 3;
    float accR[2][2][4] = {}, accZ[2][2][4] = {}, accN1[2][2][4] = {}, accN2[2][2][4] = {};

    if (t > 0) {
        DEC_PHASE(g_PI, Psz, Wih, accN1)
    }
    DEC_PHASE(Hin, Dsz, Whh, accN2)

    // GRU pointwise + writes
#pragma unroll
    for (int nf = 0; nf < 2; nf++) {
        int u = n0 + wn * 16 + nf * 8 + 2 * cq;
        float2 biR = *(const float2*)(bih + u);
        float2 biZ = *(const float2*)(bih + Dsz + u);
        float2 biN = *(const float2*)(bih + 2 * Dsz + u);
        float2 bhR = *(const float2*)(bhh + u);
        float2 bhZ = *(const float2*)(bhh + Dsz + u);
        float2 bhN = *(const float2*)(bhh + 2 * Dsz + u);
#pragma unroll
        for (int mf = 0; mf < 2; mf++) {
#pragma unroll
            for (int half = 0; half < 2; half++) {
                int m = m0 + wm * 32 + mf * 16 + r + half * 8;
                int b = m & (Bsz - 1);
                int s = m >> 9;
                float2 hold = *(const float2*)(Hin + (size_t)m * Dsz + u);
                int c0 = half * 2;
                float rx = sigmf(accR[mf][nf][c0 + 0] + biR.x + bhR.x);
                float ry = sigmf(accR[mf][nf][c0 + 1] + biR.y + bhR.y);
                float zx = sigmf(accZ[mf][nf][c0 + 0] + biZ.x + bhZ.x);
                float zy = sigmf(accZ[mf][nf][c0 + 1] + biZ.y + bhZ.y);
                float nx = tanhf(accN1[mf][nf][c0 + 0] + biN.x + rx * (accN2[mf][nf][c0 + 0] + bhN.x));
                float ny = tanhf(accN1[mf][nf][c0 + 1] + biN.y + ry * (accN2[mf][nf][c0 + 1] + bhN.y));
                float2 o;
                o.x = nx + zx * (hold.x - nx);
                o.y = ny + zy * (hold.y - ny);
                *(float2*)(Hout + (size_t)m * Dsz + u) = o;
                *(float2*)(dech + (((size_t)b * Ssz + s) * Tsz + t) * Dsz + u) = o;
            }
        }
    }
}

// ---------------- out = tanh(h @ W_h2p + b), N = 4 ----------------
__global__ void out_kernel(const float* __restrict__ Hcur,
                           const float* __restrict__ W, const float* __restrict__ bias,
                           float* __restrict__ preds, int t)
{
    int gtid = blockIdx.x * blockDim.x + threadIdx.x;
    int warp = gtid >> 5;
    int lane = threadIdx.x & 31;
    if (warp >= NROWS) return;
    const float* h = Hcur + (size_t)warp * Dsz;
    float ax = 0.f, ay = 0.f, az = 0.f, aw = 0.f;
    for (int d = lane; d < Dsz; d += 32) {
        float hv = h[d];
        float4 w = *(const float4*)(W + (size_t)d * 4);
        ax = fmaf(hv, w.x, ax); ay = fmaf(hv, w.y, ay);
        az = fmaf(hv, w.z, az); aw = fmaf(hv, w.w, aw);
    }
#pragma unroll
    for (int o = 16; o > 0; o >>= 1) {
        ax += __shfl_xor_sync(0xFFFFFFFFu, ax, o);
        ay += __shfl_xor_sync(0xFFFFFFFFu, ay, o);
        az += __shfl_xor_sync(0xFFFFFFFFu, az, o);
        aw += __shfl_xor_sync(0xFFFFFFFFu, aw, o);
    }
    if (lane == 0) {
        int b = warp & (Bsz - 1);
        int s = warp >> 9;
        float4 o;
        o.x = tanhf(ax + bias[0]);
        o.y = tanhf(ay + bias[1]);
        o.z = tanhf(az + bias[2]);
        o.w = tanhf(aw + bias[3]);
        *(float4*)(preds + (((size_t)b * Ssz + s) * Tsz + t) * 4) = o;
    }
}

// ---------------- host ----------------
extern "C" void kernel_launch(void* const* d_in, const int* in_sizes, int n_in,
                              void* d_out, int out_size)
{
    const float* box      = (const float*)d_in[0];
    const float* dm       = (const float*)d_in[1];
    const float* Wbe      = (const float*)d_in[2];
    const float* bbe      = (const float*)d_in[3];
    const float* Wde      = (const float*)d_in[4];
    const float* bde      = (const float*)d_in[5];
    const float* Wih_box  = (const float*)d_in[6];
    const float* Whh_box  = (const float*)d_in[7];
    const float* bih_box  = (const float*)d_in[8];
    const float* bhh_box  = (const float*)d_in[9];
    const float* Wih_dm   = (const float*)d_in[10];
    const float* Whh_dm   = (const float*)d_in[11];
    const float* bih_dm   = (const float*)d_in[12];
    const float* bhh_dm   = (const float*)d_in[13];
    const float* Wih_dec  = (const float*)d_in[14];
    const float* Whh_dec  = (const float*)d_in[15];
    const float* bih_dec  = (const float*)d_in[16];
    const float* bhh_dec  = (const float*)d_in[17];
    const float* W_h2pi   = (const float*)d_in[18];
    const float* b_h2pi   = (const float*)d_in[19];
    const float* W_h2p    = (const float*)d_in[20];
    const float* b_h2p    = (const float*)d_in[21];

    float* preds = (float*)d_out;                                      // [B,S,T,4]
    float* dech  = (float*)d_out + (size_t)Bsz * Ssz * Tsz * PDsz;     // [B,S,T,D]

    void *p_emb, *p_gi, *p_hbuf, *p_H;
    cudaGetSymbolAddress(&p_emb, g_emb);
    cudaGetSymbolAddress(&p_gi, g_gi);
    cudaGetSymbolAddress(&p_hbuf, g_hbuf);
    cudaGetSymbolAddress(&p_H, g_H);
    float* emb0 = (float*)p_emb;
    float* emb1 = emb0 + (size_t)NROWS * Esz;
    float* gi0  = (float*)p_gi;
    float* gi1  = gi0 + (size_t)NROWS * G3H;
    float* H0   = (float*)p_H;
    float* H1   = H0 + (size_t)NROWS * Dsz;
    float* PI;
    { void* p; cudaGetSymbolAddress(&p, g_PI); PI = (float*)p; }

    // zero initial encoder hiddens
    cudaMemsetAsync(p_hbuf, 0, sizeof(float) * 2 * 2 * Bsz * Hsz);

    // embeddings (both encoders)
    {
        dim3 grid((NROWS * Esz + 255) / 256, 2);
        embed_kernel<<<grid, 256>>>(box, dm, Wbe, bbe, Wde, bde);
    }
    // encoder input gates: gi = emb @ Wih^T + bih (NT, tensor cores)
    {
        dim3 grid(G3H / 64, NROWS / 128);
        gemm_tf32<0, true><<<grid, 256>>>(emb0, Esz, Wih_box, bih_box, gi0, G3H);
        gemm_tf32<0, true><<<grid, 256>>>(emb1, Esz, Wih_dm,  bih_dm,  gi1, G3H);
    }
    // encoder recurrence
    for (int s = 0; s < Ssz; s++) {
        dim3 grid(Hsz / 32, Bsz / 64, 2);
        enc_step_mma<<<grid, 256>>>(s, s & 1, Whh_box, bhh_box, Whh_dm, bhh_dm, H0);
    }
    // decoder: 10 sequential steps at batch 5120
    for (int t = 0; t < Tsz; t++) {
        float* hin  = (t & 1) ? H1 : H0;
        float* hout = (t & 1) ? H0 : H1;
        {
            dim3 grid(Dsz / 32, NROWS / 128);
            dec_step_mma<<<grid, 256>>>(hin, hout, Wih_dec, Whh_dec,
                                        bih_dec, bhh_dec, dech, t);
        }
        if (t < Tsz - 1) {
            dim3 grid(Psz / 64, NROWS / 128);
            gemm_tf32<1, false><<<grid, 256>>>(hout, Dsz, W_h2pi, b_h2pi, PI, Psz);
        }
        out_kernel<<<(NROWS * 32 + 255) / 256, 256>>>(hout, W_h2p, b_h2p, preds, t);
    }
}

// round 6
// speedup vs baseline: 1.7243x; 1.4336x over previous
#include <cuda_runtime.h>
#include <math.h>
#include <stdint.h>

// Problem dims
#define Bsz 512
#define Ssz 10
#define Tsz 10
#define Esz 512
#define Hsz 512          // HB = HD
#define Dsz 1024         // dec hidden = HB + HD
#define Psz 512          // predictor input
#define PDsz 4
#define NROWS (Ssz*Bsz)  // 5120
#define G3H (3*Hsz)      // 1536

// ---------------- scratch ----------------
__device__ float g_emb[2][NROWS*Esz];
__device__ float g_gi[2][NROWS*G3H];
__device__ float g_hbuf[2][2][Bsz*Hsz];
__device__ float g_H[2][NROWS*Dsz];
__device__ float g_PI[NROWS*Psz];
__device__ float g_WpiT[Psz*Dsz];     // W_h2pi transposed to [P][D]

__device__ __forceinline__ float sigmf(float x) { return 1.0f / (1.0f + __expf(-x)); }

// tf32 split: v = hi + lo, hi = round_to_tf32(v)
__device__ __forceinline__ void split2(float v, float& hi, float& lo) {
    uint32_t h;
    asm("cvt.rna.tf32.f32 %0, %1;" : "=r"(h) : "f"(v));
    float hf = __uint_as_float(h);
    hi = hf; lo = v - hf;
}

// m16n8k8 tf32 mma: c += a(16x8 row) * b(8x8 col)
__device__ __forceinline__ void mma8(float* c, const uint32_t* a, const uint32_t* b) {
    asm("mma.sync.aligned.m16n8k8.row.col.f32.tf32.tf32.f32 "
        "{%0,%1,%2,%3}, {%4,%5,%6,%7}, {%8,%9}, {%0,%1,%2,%3};"
        : "+f"(c[0]), "+f"(c[1]), "+f"(c[2]), "+f"(c[3])
        : "r"(a[0]), "r"(a[1]), "r"(a[2]), "r"(a[3]), "r"(b[0]), "r"(b[1]));
}

__device__ __forceinline__ void cpa16(void* smem_ptr, const void* gptr) {
    uint32_t s = (uint32_t)__cvta_generic_to_shared(smem_ptr);
    asm volatile("cp.async.cg.shared.global [%0], [%1], 16;" :: "r"(s), "l"(gptr));
}
#define CPA_COMMIT asm volatile("cp.async.commit_group;")
#define CPA_WAIT1  asm volatile("cp.async.wait_group 1;")
#define CPA_WAIT0  asm volatile("cp.async.wait_group 0;")

#define ASTR 36   // tile k-stride (32 + 4 pad; 144B rows keep 16B align, conflict-free)

// split a raw float to packed hi/lo uint pair
#define SPLIT_TO(raw, HI, LO) do { float _h,_l; split2((raw),_h,_l); \
    (HI)=__float_as_uint(_h); (LO)=__float_as_uint(_l); } while(0)

// ---------------- embeddings: relu(x @ W + b), K=4 ----------------
__global__ void embed_kernel(const float* __restrict__ box, const float* __restrict__ dm,
                             const float* __restrict__ Wb, const float* __restrict__ bb,
                             const float* __restrict__ Wd, const float* __restrict__ bd)
{
    int idx = blockIdx.x * blockDim.x + threadIdx.x;
    if (idx >= NROWS * Esz) return;
    int e = idx % Esz;
    int sb = idx / Esz;
    int b = sb % Bsz, s = sb / Bsz;
    const float* x; const float* W; const float* bi; float* out;
    if (blockIdx.y == 0) { x = box; W = Wb; bi = bb; out = g_emb[0]; }
    else                 { x = dm;  W = Wd; bi = bd; out = g_emb[1]; }
    const float* xp = x + ((size_t)b * Ssz + s) * 4;
    float acc = bi[e];
#pragma unroll
    for (int k = 0; k < 4; k++) acc = fmaf(xp[k], W[(size_t)k * Esz + e], acc);
    out[idx] = fmaxf(acc, 0.0f);
}

// ---------------- transpose W_h2pi [D][P] -> [P][D] ----------------
__global__ void transpose_kernel(const float* __restrict__ W, float* __restrict__ WT)
{
    __shared__ float t[32][33];
    int bx = blockIdx.x * 32, by = blockIdx.y * 32;  // bx over P, by over D
    int x = threadIdx.x, y = threadIdx.y;            // 32 x 8
#pragma unroll
    for (int i = 0; i < 32; i += 8) t[y + i][x] = W[(size_t)(by + y + i) * Psz + bx + x];
    __syncthreads();
#pragma unroll
    for (int i = 0; i < 32; i += 8) WT[(size_t)(bx + y + i) * Dsz + by + x] = t[x][y + i];
}

// ================= pipelined NT GEMM: C[M,Nn] = A[M,K] @ B[Nn,K]^T + bias =================
// Block 128Mx64N, BK=32, 2-stage cp.async. 8 warps (4Mx2N), warp 32x32, 3xTF32.
__device__ __forceinline__ void gemm_prefetch(float* sA, float* sB,
    const float* A, const float* B, int K, int k0, int m0, int n0, int tid)
{
#pragma unroll
    for (int i = 0; i < 4; i++) {
        int f = tid + i * 256;            // 0..1023
        int m = f >> 3, c = (f & 7) * 4;
        cpa16(sA + m * ASTR + c, A + (size_t)(m0 + m) * K + k0 + c);
    }
#pragma unroll
    for (int i = 0; i < 2; i++) {
        int f = tid + i * 256;            // 0..511
        int row = f >> 3, c = (f & 7) * 4;
        cpa16(sB + row * ASTR + c, B + (size_t)(n0 + row) * K + k0 + c);
    }
}

template <int ACT>
__global__ __launch_bounds__(256) void gemm_nt_pipe(
    const float* __restrict__ A, int K,
    const float* __restrict__ B, const float* __restrict__ bias,
    float* __restrict__ C, int Nn)
{
    extern __shared__ float smem[];
    float* sA = smem;                 // 2 x 128 x 36
    float* sB = smem + 2 * 128 * ASTR;  // 2 x 64 x 36
    int tid = threadIdx.x, lane = tid & 31, wid = tid >> 5;
    int wm = wid & 3, wn = wid >> 2;
    int m0 = blockIdx.y * 128, n0 = blockIdx.x * 64;
    int r = lane >> 2, cq = lane & 3;
    float acc[2][4][4] = {};

    int nstg = K / 32;
    gemm_prefetch(sA, sB, A, B, K, 0, m0, n0, tid);
    CPA_COMMIT;
    for (int st = 0; st < nstg; st++) {
        float* Asb = sA + (st & 1) * (128 * ASTR);
        float* Bsb = sB + (st & 1) * (64 * ASTR);
        if (st + 1 < nstg) {
            gemm_prefetch(sA + ((st + 1) & 1) * (128 * ASTR), sB + ((st + 1) & 1) * (64 * ASTR),
                          A, B, K, (st + 1) * 32, m0, n0, tid);
            CPA_COMMIT; CPA_WAIT1;
        } else { CPA_WAIT0; }
        __syncthreads();
#pragma unroll
        for (int kk = 0; kk < 32; kk += 8) {
            uint32_t ah[2][4], al[2][4];
#pragma unroll
            for (int mf = 0; mf < 2; mf++) {
                int mb = wm * 32 + mf * 16 + r;
                SPLIT_TO(Asb[mb * ASTR + kk + cq],           ah[mf][0], al[mf][0]);
                SPLIT_TO(Asb[(mb + 8) * ASTR + kk + cq],     ah[mf][1], al[mf][1]);
                SPLIT_TO(Asb[mb * ASTR + kk + cq + 4],       ah[mf][2], al[mf][2]);
                SPLIT_TO(Asb[(mb + 8) * ASTR + kk + cq + 4], ah[mf][3], al[mf][3]);
            }
#pragma unroll
            for (int nf = 0; nf < 4; nf++) {
                int nb = wn * 32 + nf * 8 + r;
                uint32_t bh[2], bl[2];
                SPLIT_TO(Bsb[nb * ASTR + kk + cq],     bh[0], bl[0]);
                SPLIT_TO(Bsb[nb * ASTR + kk + cq + 4], bh[1], bl[1]);
#pragma unroll
                for (int mf = 0; mf < 2; mf++) {
                    mma8(acc[mf][nf], ah[mf], bh);
                    mma8(acc[mf][nf], ah[mf], bl);
                    mma8(acc[mf][nf], al[mf], bh);
                }
            }
        }
        __syncthreads();
    }
#pragma unroll
    for (int nf = 0; nf < 4; nf++) {
        int u = n0 + wn * 32 + nf * 8 + 2 * cq;
        float2 bi2 = *(const float2*)(bias + u);
#pragma unroll
        for (int mf = 0; mf < 2; mf++) {
#pragma unroll
            for (int half = 0; half < 2; half++) {
                int m = m0 + wm * 32 + mf * 16 + r + half * 8;
                float vx = acc[mf][nf][half * 2 + 0] + bi2.x;
                float vy = acc[mf][nf][half * 2 + 1] + bi2.y;
                if (ACT == 1) { vx = fmaxf(vx, 0.0f); vy = fmaxf(vy, 0.0f); }
                float2 o = {vx, vy};
                *(float2*)(C + (size_t)m * Nn + u) = o;
            }
        }
    }
}

// ================= encoder recurrent step (pipelined, fused GRU) =================
// Block 64Mx32N units, BK=32, 2-stage. 8 warps (2Mx4N), warp 32Mx8N, 3 gates.
__device__ __forceinline__ void enc_prefetch(float* sA, float* sB,
    const float* hin, const float* Whh, int k0, int m0, int n0, int tid)
{
#pragma unroll
    for (int i = 0; i < 2; i++) {
        int f = tid + i * 256;            // 0..511
        int m = f >> 3, c = (f & 7) * 4;
        cpa16(sA + m * ASTR + c, hin + (size_t)(m0 + m) * Hsz + k0 + c);
    }
#pragma unroll
    for (int i = 0; i < 3; i++) {
        int f = tid + i * 256;            // 0..767
        int row = f >> 3, c = (f & 7) * 4;
        int g = row >> 5, nn = row & 31;
        cpa16(sB + row * ASTR + c, Whh + (size_t)(g * Hsz + n0 + nn) * Hsz + k0 + c);
    }
}

__global__ __launch_bounds__(256) void enc_step_mma(
    int s, int par,
    const float* __restrict__ Whh0, const float* __restrict__ bhh0,
    const float* __restrict__ Whh1, const float* __restrict__ bhh1,
    float* __restrict__ H0out)
{
    __shared__ float sA[2][64 * ASTR];
    __shared__ float sB[2][96 * ASTR];
    int z = blockIdx.z;
    const float* Whh = z ? Whh1 : Whh0;
    const float* bhh = z ? bhh1 : bhh0;
    const float* hin = g_hbuf[z][par];
    float* hout = g_hbuf[z][par ^ 1];
    const float* gi = g_gi[z] + (size_t)s * Bsz * G3H;

    int tid = threadIdx.x, lane = tid & 31, wid = tid >> 5;
    int wm = wid & 1, wn = wid >> 1;
    int m0 = blockIdx.y * 64, n0 = blockIdx.x * 32;
    int r = lane >> 2, cq = lane & 3;
    float accR[2][4] = {}, accZ[2][4] = {}, accN[2][4] = {};

    int nstg = Hsz / 32;
    enc_prefetch(sA[0], sB[0], hin, Whh, 0, m0, n0, tid);
    CPA_COMMIT;
    for (int st = 0; st < nstg; st++) {
        float* Asb = sA[st & 1];
        float* Bsb = sB[st & 1];
        if (st + 1 < nstg) {
            enc_prefetch(sA[(st + 1) & 1], sB[(st + 1) & 1], hin, Whh, (st + 1) * 32, m0, n0, tid);
            CPA_COMMIT; CPA_WAIT1;
        } else { CPA_WAIT0; }
        __syncthreads();
#pragma unroll
        for (int kk = 0; kk < 32; kk += 8) {
            uint32_t ah[2][4], al[2][4];
#pragma unroll
            for (int mf = 0; mf < 2; mf++) {
                int mb = wm * 32 + mf * 16 + r;
                SPLIT_TO(Asb[mb * ASTR + kk + cq],           ah[mf][0], al[mf][0]);
                SPLIT_TO(Asb[(mb + 8) * ASTR + kk + cq],     ah[mf][1], al[mf][1]);
                SPLIT_TO(Asb[mb * ASTR + kk + cq + 4],       ah[mf][2], al[mf][2]);
                SPLIT_TO(Asb[(mb + 8) * ASTR + kk + cq + 4], ah[mf][3], al[mf][3]);
            }
#pragma unroll
            for (int g = 0; g < 3; g++) {
                int nb = g * 32 + wn * 8 + r;
                uint32_t bh[2], bl[2];
                SPLIT_TO(Bsb[nb * ASTR + kk + cq],     bh[0], bl[0]);
                SPLIT_TO(Bsb[nb * ASTR + kk + cq + 4], bh[1], bl[1]);
#pragma unroll
                for (int mf = 0; mf < 2; mf++) {
                    float* cc = (g == 0) ? accR[mf] : (g == 1) ? accZ[mf] : accN[mf];
                    mma8(cc, ah[mf], bh);
                    mma8(cc, ah[mf], bl);
                    mma8(cc, al[mf], bh);
                }
            }
        }
        __syncthreads();
    }
    // epilogue
    int u = n0 + wn * 8 + 2 * cq;
    float2 bR = *(const float2*)(bhh + u);
    float2 bZ = *(const float2*)(bhh + Hsz + u);
    float2 bN = *(const float2*)(bhh + 2 * Hsz + u);
#pragma unroll
    for (int mf = 0; mf < 2; mf++) {
#pragma unroll
        for (int half = 0; half < 2; half++) {
            int m = m0 + wm * 32 + mf * 16 + r + half * 8;
            float2 giR = *(const float2*)(gi + (size_t)m * G3H + u);
            float2 giZ = *(const float2*)(gi + (size_t)m * G3H + Hsz + u);
            float2 giN = *(const float2*)(gi + (size_t)m * G3H + 2 * Hsz + u);
            float2 hold = *(const float2*)(hin + (size_t)m * Hsz + u);
            int c0 = half * 2;
            float rx = sigmf(giR.x + accR[mf][c0 + 0] + bR.x);
            float ry = sigmf(giR.y + accR[mf][c0 + 1] + bR.y);
            float zx = sigmf(giZ.x + accZ[mf][c0 + 0] + bZ.x);
            float zy = sigmf(giZ.y + accZ[mf][c0 + 1] + bZ.y);
            float nx = tanhf(giN.x + rx * (accN[mf][c0 + 0] + bN.x));
            float ny = tanhf(giN.y + ry * (accN[mf][c0 + 1] + bN.y));
            float2 o;
            o.x = nx + zx * (hold.x - nx);
            o.y = ny + zy * (hold.y - ny);
            *(float2*)(hout + (size_t)m * Hsz + u) = o;
            *(float2*)(H0out + ((size_t)s * Bsz + m) * Dsz + (size_t)z * Hsz + u) = o;
        }
    }
}

// ================= decoder step (pipelined, fused two-phase GRU) =================
// Block 128Mx32N units, BK=32, 2-stage. 8 warps (4Mx2N), warp 32Mx16N, 3 gates x 2 phases.
__device__ __forceinline__ void dec_prefetch(float* sA, float* sB,
    const float* A, const float* W, int K, int k0, int m0, int n0, int tid)
{
#pragma unroll
    for (int i = 0; i < 4; i++) {
        int f = tid + i * 256;            // 0..1023
        int m = f >> 3, c = (f & 7) * 4;
        cpa16(sA + m * ASTR + c, A + (size_t)(m0 + m) * K + k0 + c);
    }
#pragma unroll
    for (int i = 0; i < 3; i++) {
        int f = tid + i * 256;            // 0..767
        int row = f >> 3, c = (f & 7) * 4;
        int g = row >> 5, nn = row & 31;
        cpa16(sB + row * ASTR + c, W + (size_t)(g * Dsz + n0 + nn) * K + k0 + c);
    }
}

#define DEC_COMPUTE(Asb, Bsb, ACCN)                                              \
    _Pragma("unroll") for (int kk = 0; kk < 32; kk += 8) {                       \
        uint32_t ah[2][4], al[2][4];                                             \
        _Pragma("unroll") for (int mf = 0; mf < 2; mf++) {                       \
            int mb = wm * 32 + mf * 16 + r;                                      \
            SPLIT_TO((Asb)[mb * ASTR + kk + cq],           ah[mf][0], al[mf][0]);\
            SPLIT_TO((Asb)[(mb + 8) * ASTR + kk + cq],     ah[mf][1], al[mf][1]);\
            SPLIT_TO((Asb)[mb * ASTR + kk + cq + 4],       ah[mf][2], al[mf][2]);\
            SPLIT_TO((Asb)[(mb + 8) * ASTR + kk + cq + 4], ah[mf][3], al[mf][3]);\
        }                                                                        \
        _Pragma("unroll") for (int g = 0; g < 3; g++) {                          \
            _Pragma("unroll") for (int nf = 0; nf < 2; nf++) {                   \
                int nb = g * 32 + wn * 16 + nf * 8 + r;                          \
                uint32_t bh[2], bl[2];                                           \
                SPLIT_TO((Bsb)[nb * ASTR + kk + cq],     bh[0], bl[0]);          \
                SPLIT_TO((Bsb)[nb * ASTR + kk + cq + 4], bh[1], bl[1]);          \
                _Pragma("unroll") for (int mf = 0; mf < 2; mf++) {               \
                    float* cc = (g == 0) ? accR[mf][nf]                          \
                              : (g == 1) ? accZ[mf][nf] : (ACCN)[mf][nf];        \
                    mma8(cc, ah[mf], bh);                                        \
                    mma8(cc, ah[mf], bl);                                        \
                    mma8(cc, al[mf], bh);                                        \
                }                                                                \
            }                                                                    \
        }                                                                        \
    }

#define DEC_PIPE(APTR, KDIM, WPTR, ACCN)                                         \
    {                                                                            \
        int nstg = (KDIM) / 32;                                                  \
        dec_prefetch(sA, sB, (APTR), (WPTR), (KDIM), 0, m0, n0, tid);            \
        CPA_COMMIT;                                                              \
        for (int st = 0; st < nstg; st++) {                                      \
            float* Asb = sA + (st & 1) * (128 * ASTR);                           \
            float* Bsb = sB + (st & 1) * (96 * ASTR);                            \
            if (st + 1 < nstg) {                                                 \
                dec_prefetch(sA + ((st + 1) & 1) * (128 * ASTR),                 \
                             sB + ((st + 1) & 1) * (96 * ASTR),                  \
                             (APTR), (WPTR), (KDIM), (st + 1) * 32, m0, n0, tid);\
                CPA_COMMIT; CPA_WAIT1;                                           \
            } else { CPA_WAIT0; }                                                \
            __syncthreads();                                                     \
            DEC_COMPUTE(Asb, Bsb, ACCN)                                          \
            __syncthreads();                                                     \
        }                                                                        \
    }

__global__ __launch_bounds__(256) void dec_step_mma(
    const float* __restrict__ Hin, float* __restrict__ Hout,
    const float* __restrict__ Wih, const float* __restrict__ Whh,
    const float* __restrict__ bih, const float* __restrict__ bhh,
    float* __restrict__ dech, int t)
{
    extern __shared__ float smem[];
    float* sA = smem;                      // 2 x 128 x 36
    float* sB = smem + 2 * 128 * ASTR;     // 2 x 96 x 36
    int tid = threadIdx.x, lane = tid & 31, wid = tid >> 5;
    int wm = wid & 3, wn = wid >> 2;
    int m0 = blockIdx.y * 128, n0 = blockIdx.x * 32;
    int r = lane >> 2, cq = lane & 3;
    float accR[2][2][4] = {}, accZ[2][2][4] = {}, accN1[2][2][4] = {}, accN2[2][2][4] = {};

    if (t > 0) {
        DEC_PIPE(g_PI, Psz, Wih, accN1)
    }
    DEC_PIPE(Hin, Dsz, Whh, accN2)

    // GRU pointwise + writes
#pragma unroll
    for (int nf = 0; nf < 2; nf++) {
        int u = n0 + wn * 16 + nf * 8 + 2 * cq;
        float2 biR = *(const float2*)(bih + u);
        float2 biZ = *(const float2*)(bih + Dsz + u);
        float2 biN = *(const float2*)(bih + 2 * Dsz + u);
        float2 bhR = *(const float2*)(bhh + u);
        float2 bhZ = *(const float2*)(bhh + Dsz + u);
        float2 bhN = *(const float2*)(bhh + 2 * Dsz + u);
#pragma unroll
        for (int mf = 0; mf < 2; mf++) {
#pragma unroll
            for (int half = 0; half < 2; half++) {
                int m = m0 + wm * 32 + mf * 16 + r + half * 8;
                int b = m & (Bsz - 1);
                int s = m >> 9;
                float2 hold = *(const float2*)(Hin + (size_t)m * Dsz + u);
                int c0 = half * 2;
                float rx = sigmf(accR[mf][nf][c0 + 0] + biR.x + bhR.x);
                float ry = sigmf(accR[mf][nf][c0 + 1] + biR.y + bhR.y);
                float zx = sigmf(accZ[mf][nf][c0 + 0] + biZ.x + bhZ.x);
                float zy = sigmf(accZ[mf][nf][c0 + 1] + biZ.y + bhZ.y);
                float nx = tanhf(accN1[mf][nf][c0 + 0] + biN.x + rx * (accN2[mf][nf][c0 + 0] + bhN.x));
                float ny = tanhf(accN1[mf][nf][c0 + 1] + biN.y + ry * (accN2[mf][nf][c0 + 1] + bhN.y));
                float2 o;
                o.x = nx + zx * (hold.x - nx);
                o.y = ny + zy * (hold.y - ny);
                *(float2*)(Hout + (size_t)m * Dsz + u) = o;
                *(float2*)(dech + (((size_t)b * Ssz + s) * Tsz + t) * Dsz + u) = o;
            }
        }
    }
}

// ---------------- out = tanh(h @ W_h2p + b), N = 4 ----------------
__global__ void out_kernel(const float* __restrict__ Hcur,
                           const float* __restrict__ W, const float* __restrict__ bias,
                           float* __restrict__ preds, int t)
{
    int gtid = blockIdx.x * blockDim.x + threadIdx.x;
    int warp = gtid >> 5;
    int lane = threadIdx.x & 31;
    if (warp >= NROWS) return;
    const float* h = Hcur + (size_t)warp * Dsz;
    float ax = 0.f, ay = 0.f, az = 0.f, aw = 0.f;
    for (int d = lane; d < Dsz; d += 32) {
        float hv = h[d];
        float4 w = *(const float4*)(W + (size_t)d * 4);
        ax = fmaf(hv, w.x, ax); ay = fmaf(hv, w.y, ay);
        az = fmaf(hv, w.z, az); aw = fmaf(hv, w.w, aw);
    }
#pragma unroll
    for (int o = 16; o > 0; o >>= 1) {
        ax += __shfl_xor_sync(0xFFFFFFFFu, ax, o);
        ay += __shfl_xor_sync(0xFFFFFFFFu, ay, o);
        az += __shfl_xor_sync(0xFFFFFFFFu, az, o);
        aw += __shfl_xor_sync(0xFFFFFFFFu, aw, o);
    }
    if (lane == 0) {
        int b = warp & (Bsz - 1);
        int s = warp >> 9;
        float4 o;
        o.x = tanhf(ax + bias[0]);
        o.y = tanhf(ay + bias[1]);
        o.z = tanhf(az + bias[2]);
        o.w = tanhf(aw + bias[3]);
        *(float4*)(preds + (((size_t)b * Ssz + s) * Tsz + t) * 4) = o;
    }
}

// ---------------- host ----------------
#define DEC_SMEM ((2*128*ASTR + 2*96*ASTR) * (int)sizeof(float))   // 64512
#define GEMM_SMEM ((2*128*ASTR + 2*64*ASTR) * (int)sizeof(float))  // 55296

extern "C" void kernel_launch(void* const* d_in, const int* in_sizes, int n_in,
                              void* d_out, int out_size)
{
    const float* box      = (const float*)d_in[0];
    const float* dm       = (const float*)d_in[1];
    const float* Wbe      = (const float*)d_in[2];
    const float* bbe      = (const float*)d_in[3];
    const float* Wde      = (const float*)d_in[4];
    const float* bde      = (const float*)d_in[5];
    const float* Wih_box  = (const float*)d_in[6];
    const float* Whh_box  = (const float*)d_in[7];
    const float* bih_box  = (const float*)d_in[8];
    const float* bhh_box  = (const float*)d_in[9];
    const float* Wih_dm   = (const float*)d_in[10];
    const float* Whh_dm   = (const float*)d_in[11];
    const float* bih_dm   = (const float*)d_in[12];
    const float* bhh_dm   = (const float*)d_in[13];
    const float* Wih_dec  = (const float*)d_in[14];
    const float* Whh_dec  = (const float*)d_in[15];
    const float* bih_dec  = (const float*)d_in[16];
    const float* bhh_dec  = (const float*)d_in[17];
    const float* W_h2pi   = (const float*)d_in[18];
    const float* b_h2pi   = (const float*)d_in[19];
    const float* W_h2p    = (const float*)d_in[20];
    const float* b_h2p    = (const float*)d_in[21];

    float* preds = (float*)d_out;                                      // [B,S,T,4]
    float* dech  = (float*)d_out + (size_t)Bsz * Ssz * Tsz * PDsz;     // [B,S,T,D]

    void *p_emb, *p_gi, *p_hbuf, *p_H, *p_PI, *p_WT;
    cudaGetSymbolAddress(&p_emb, g_emb);
    cudaGetSymbolAddress(&p_gi, g_gi);
    cudaGetSymbolAddress(&p_hbuf, g_hbuf);
    cudaGetSymbolAddress(&p_H, g_H);
    cudaGetSymbolAddress(&p_PI, g_PI);
    cudaGetSymbolAddress(&p_WT, g_WpiT);
    float* emb0 = (float*)p_emb;
    float* emb1 = emb0 + (size_t)NROWS * Esz;
    float* gi0  = (float*)p_gi;
    float* gi1  = gi0 + (size_t)NROWS * G3H;
    float* H0   = (float*)p_H;
    float* H1   = H0 + (size_t)NROWS * Dsz;
    float* PI   = (float*)p_PI;
    float* WpiT = (float*)p_WT;

    cudaFuncSetAttribute(dec_step_mma, cudaFuncAttributeMaxDynamicSharedMemorySize, DEC_SMEM);
    cudaFuncSetAttribute(gemm_nt_pipe<0>, cudaFuncAttributeMaxDynamicSharedMemorySize, GEMM_SMEM);
    cudaFuncSetAttribute(gemm_nt_pipe<1>, cudaFuncAttributeMaxDynamicSharedMemorySize, GEMM_SMEM);

    // zero initial encoder hiddens
    cudaMemsetAsync(p_hbuf, 0, sizeof(float) * 2 * 2 * Bsz * Hsz);

    // embeddings + weight transpose
    {
        dim3 grid((NROWS * Esz + 255) / 256, 2);
        embed_kernel<<<grid, 256>>>(box, dm, Wbe, bbe, Wde, bde);
        dim3 tg(Psz / 32, Dsz / 32);
        transpose_kernel<<<tg, dim3(32, 8)>>>(W_h2pi, WpiT);
    }
    // encoder input gates: gi = emb @ Wih^T + bih
    {
        dim3 grid(G3H / 64, NROWS / 128);
        gemm_nt_pipe<0><<<grid, 256, GEMM_SMEM>>>(emb0, Esz, Wih_box, bih_box, gi0, G3H);
        gemm_nt_pipe<0><<<grid, 256, GEMM_SMEM>>>(emb1, Esz, Wih_dm,  bih_dm,  gi1, G3H);
    }
    // encoder recurrence
    for (int s = 0; s < Ssz; s++) {
        dim3 grid(Hsz / 32, Bsz / 64, 2);
        enc_step_mma<<<grid, 256>>>(s, s & 1, Whh_box, bhh_box, Whh_dm, bhh_dm, H0);
    }
    // decoder: 10 sequential steps at batch 5120
    for (int t = 0; t < Tsz; t++) {
        float* hin  = (t & 1) ? H1 : H0;
        float* hout = (t & 1) ? H0 : H1;
        {
            dim3 grid(Dsz / 32, NROWS / 128);
            dec_step_mma<<<grid, 256, DEC_SMEM>>>(hin, hout, Wih_dec, Whh_dec,
                                                  bih_dec, bhh_dec, dech, t);
        }
        if (t < Tsz - 1) {
            dim3 grid(Psz / 64, NROWS / 128);
            gemm_nt_pipe<1><<<grid, 256, GEMM_SMEM>>>(hout, Dsz, WpiT, b_h2pi, PI, Psz);
        }
        out_kernel<<<(NROWS * 32 + 255) / 256, 256>>>(hout, W_h2p, b_h2p, preds, t);
    }
}